// round 1
// baseline (speedup 1.0000x reference)
#include <cuda_runtime.h>
#include <math.h>

#define DIMC 1024
#define HD 64
#define NH 16
#define BATCH 2
#define NQ 1024
#define MKV 2048
#define ATT_SCALE 0.125f

// Scratch (no allocations allowed in kernel_launch)
__device__ __align__(16) float g_Q[(size_t)BATCH * NQ * DIMC];        // 8 MB
__device__ __align__(16) float g_KV[(size_t)BATCH * MKV * 2 * DIMC];  // 32 MB
__device__ __align__(16) float g_AO[(size_t)BATCH * NQ * DIMC];       // 8 MB

// ---------------------------------------------------------------------------
// GEMM: C[M,N] = A[M,K] @ B[N,K]^T (+ bias[col]); A,B row-major.
// 128x128 block tile, BK=32, 256 threads, 8x8 micro-tile per thread.
// ---------------------------------------------------------------------------
#define BM 128
#define BN 128
#define BKK 32
#define LDT 132  // padded leading dim for smem tiles

__global__ __launch_bounds__(256) void gemm_bias_k(
    const float* __restrict__ A, const float* __restrict__ B,
    const float* __restrict__ bias, float* __restrict__ C,
    int Mrows, int Ncols, int K)
{
    __shared__ float As[BKK][LDT];
    __shared__ float Bs[BKK][LDT];
    const int bm = blockIdx.y * BM;
    const int bn = blockIdx.x * BN;
    const int tid = threadIdx.x;
    const int tx = tid & 15, ty = tid >> 4;

    float acc[8][8];
#pragma unroll
    for (int i = 0; i < 8; i++)
#pragma unroll
        for (int j = 0; j < 8; j++) acc[i][j] = 0.f;

    for (int k0 = 0; k0 < K; k0 += BKK) {
#pragma unroll
        for (int i = 0; i < 4; i++) {
            int f = tid + i * 256;
            int r = f >> 3;
            int c4 = (f & 7) << 2;
            float4 va = *(const float4*)(A + (size_t)(bm + r) * K + k0 + c4);
            As[c4 + 0][r] = va.x; As[c4 + 1][r] = va.y;
            As[c4 + 2][r] = va.z; As[c4 + 3][r] = va.w;
            float4 vb = *(const float4*)(B + (size_t)(bn + r) * K + k0 + c4);
            Bs[c4 + 0][r] = vb.x; Bs[c4 + 1][r] = vb.y;
            Bs[c4 + 2][r] = vb.z; Bs[c4 + 3][r] = vb.w;
        }
        __syncthreads();
#pragma unroll
        for (int kk = 0; kk < BKK; kk++) {
            float4 a0 = *(const float4*)&As[kk][ty * 8];
            float4 a1 = *(const float4*)&As[kk][ty * 8 + 4];
            float4 b0 = *(const float4*)&Bs[kk][tx * 8];
            float4 b1 = *(const float4*)&Bs[kk][tx * 8 + 4];
            float a[8] = {a0.x, a0.y, a0.z, a0.w, a1.x, a1.y, a1.z, a1.w};
            float b[8] = {b0.x, b0.y, b0.z, b0.w, b1.x, b1.y, b1.z, b1.w};
#pragma unroll
            for (int i = 0; i < 8; i++)
#pragma unroll
                for (int j = 0; j < 8; j++)
                    acc[i][j] = fmaf(a[i], b[j], acc[i][j]);
        }
        __syncthreads();
    }

#pragma unroll
    for (int i = 0; i < 8; i++) {
        int row = bm + ty * 8 + i;
#pragma unroll
        for (int j = 0; j < 8; j++) {
            int col = bn + tx * 8 + j;
            float v = acc[i][j];
            if (bias) v += bias[col];
            C[(size_t)row * Ncols + col] = v;
        }
    }
}

// ---------------------------------------------------------------------------
// Flash attention: one block = (b, h, 64-row Q tile). 256 threads.
// Online softmax over M=2048 in 64-key tiles. All fp32.
// ---------------------------------------------------------------------------
#define TQ 64
#define TK 64
#define LQD 65  // HD+1 pad
#define LSK 65  // TK+1 pad

// smem floats: Q + K + V tiles (3*64*65) + S (64*65) + m/l/alpha (3*64)
#define ATTN_SMEM_FLOATS (4 * TQ * LQD + 3 * TQ)
#define ATTN_SMEM_BYTES (ATTN_SMEM_FLOATS * 4)

__global__ __launch_bounds__(256) void attn_k(
    const float* __restrict__ Q, const float* __restrict__ KV,
    const unsigned int* __restrict__ mask, float* __restrict__ AO)
{
    extern __shared__ float sm[];
    float* Qs = sm;                       // [TQ][LQD]
    float* Ks = Qs + TQ * LQD;            // [TK][LQD]
    float* Vs = Ks + TK * LQD;            // [TK][LQD]
    float* Ss = Vs + TK * LQD;            // [TQ][LSK]
    float* m_s = Ss + TQ * LSK;           // [TQ]
    float* l_s = m_s + TQ;                // [TQ]
    float* a_s = l_s + TQ;                // [TQ]

    const int qb = blockIdx.x;
    const int h  = blockIdx.y;
    const int b  = blockIdx.z;
    const int tid = threadIdx.x;
    const int tx = tid & 15, ty = tid >> 4;
    const int n0 = qb * TQ;

    // Load Q tile: rows n0..n0+63, cols h*64..h*64+63
    for (int i = tid; i < TQ * (HD / 4); i += 256) {
        int r = i >> 4;
        int c4 = (i & 15) << 2;
        float4 v = *(const float4*)(Q + ((size_t)(b * NQ + n0 + r)) * DIMC + h * HD + c4);
        float* dst = &Qs[r * LQD + c4];
        dst[0] = v.x; dst[1] = v.y; dst[2] = v.z; dst[3] = v.w;
    }
    if (tid < TQ) { m_s[tid] = -1e30f; l_s[tid] = 0.f; }

    float o[4][4];
#pragma unroll
    for (int i = 0; i < 4; i++)
#pragma unroll
        for (int j = 0; j < 4; j++) o[i][j] = 0.f;

    __syncthreads();

    for (int m0 = 0; m0 < MKV; m0 += TK) {
        // Load K and V tiles
        for (int i = tid; i < TK * (HD / 4); i += 256) {
            int r = i >> 4;
            int c4 = (i & 15) << 2;
            size_t base = ((size_t)(b * MKV + m0 + r)) * (2 * DIMC) + h * HD + c4;
            float4 kk4 = *(const float4*)(KV + base);
            float* kd = &Ks[r * LQD + c4];
            kd[0] = kk4.x; kd[1] = kk4.y; kd[2] = kk4.z; kd[3] = kk4.w;
            float4 vv4 = *(const float4*)(KV + base + DIMC);
            float* vd = &Vs[r * LQD + c4];
            vd[0] = vv4.x; vd[1] = vv4.y; vd[2] = vv4.z; vd[3] = vv4.w;
        }
        __syncthreads();

        // S = Q @ K^T (each thread 4x4)
        float acc[4][4];
#pragma unroll
        for (int i = 0; i < 4; i++)
#pragma unroll
            for (int j = 0; j < 4; j++) acc[i][j] = 0.f;

        for (int d = 0; d < HD; d++) {
            float a[4], bb[4];
#pragma unroll
            for (int i = 0; i < 4; i++) a[i] = Qs[(ty * 4 + i) * LQD + d];
#pragma unroll
            for (int j = 0; j < 4; j++) bb[j] = Ks[(tx * 4 + j) * LQD + d];
#pragma unroll
            for (int i = 0; i < 4; i++)
#pragma unroll
                for (int j = 0; j < 4; j++)
                    acc[i][j] = fmaf(a[i], bb[j], acc[i][j]);
        }

        // scale + mask, write to Ss
#pragma unroll
        for (int i = 0; i < 4; i++) {
            int gn = n0 + ty * 4 + i;
#pragma unroll
            for (int j = 0; j < 4; j++) {
                int gm = m0 + tx * 4 + j;
                unsigned int mk = mask[((size_t)b * NQ + gn) * MKV + gm];
                Ss[(ty * 4 + i) * LSK + tx * 4 + j] =
                    mk ? acc[i][j] * ATT_SCALE : -1e30f;
            }
        }
        __syncthreads();

        // Per-row online softmax: warp w owns rows w*8..w*8+7
        {
            int w = tid >> 5, lane = tid & 31;
            for (int rr = 0; rr < 8; rr++) {
                int r = w * 8 + rr;
                float v1 = Ss[r * LSK + lane];
                float v2 = Ss[r * LSK + lane + 32];
                float mx = fmaxf(v1, v2);
#pragma unroll
                for (int off = 16; off; off >>= 1)
                    mx = fmaxf(mx, __shfl_xor_sync(0xffffffffu, mx, off));
                float m_old = m_s[r];
                float m_new = fmaxf(m_old, mx);
                float p1 = __expf(v1 - m_new);
                float p2 = __expf(v2 - m_new);
                Ss[r * LSK + lane] = p1;
                Ss[r * LSK + lane + 32] = p2;
                float s = p1 + p2;
#pragma unroll
                for (int off = 16; off; off >>= 1)
                    s += __shfl_xor_sync(0xffffffffu, s, off);
                if (lane == 0) {
                    float alpha = __expf(m_old - m_new);
                    l_s[r] = l_s[r] * alpha + s;
                    m_s[r] = m_new;
                    a_s[r] = alpha;
                }
            }
        }
        __syncthreads();

        // O = O*alpha + P @ V
        float al[4];
#pragma unroll
        for (int i = 0; i < 4; i++) al[i] = a_s[ty * 4 + i];
#pragma unroll
        for (int i = 0; i < 4; i++)
#pragma unroll
            for (int j = 0; j < 4; j++) o[i][j] *= al[i];

        for (int kk = 0; kk < TK; kk++) {
            float p[4], vv[4];
#pragma unroll
            for (int i = 0; i < 4; i++) p[i] = Ss[(ty * 4 + i) * LSK + kk];
#pragma unroll
            for (int j = 0; j < 4; j++) vv[j] = Vs[kk * LQD + tx * 4 + j];
#pragma unroll
            for (int i = 0; i < 4; i++)
#pragma unroll
                for (int j = 0; j < 4; j++)
                    o[i][j] = fmaf(p[i], vv[j], o[i][j]);
        }
        __syncthreads();
    }

    // Normalize and write to g_AO (layout [b*NQ+n, h*64+d])
#pragma unroll
    for (int i = 0; i < 4; i++) {
        int r = ty * 4 + i;
        float inv = 1.0f / l_s[r];
#pragma unroll
        for (int j = 0; j < 4; j++) {
            AO[((size_t)(b * NQ + n0 + r)) * DIMC + h * HD + tx * 4 + j] = o[i][j] * inv;
        }
    }
}

// ---------------------------------------------------------------------------
// Launch
// ---------------------------------------------------------------------------
extern "C" void kernel_launch(void* const* d_in, const int* in_sizes, int n_in,
                              void* d_out, int out_size)
{
    const float* x        = (const float*)d_in[0];
    const float* context  = (const float*)d_in[1];
    const unsigned int* mask = (const unsigned int*)d_in[2];
    const float* Wq       = (const float*)d_in[3];
    const float* Wkv      = (const float*)d_in[4];
    const float* b_kv     = (const float*)d_in[5];
    const float* Wo       = (const float*)d_in[6];
    float* out            = (float*)d_out;

    float *qptr, *kvptr, *aoptr;
    cudaGetSymbolAddress((void**)&qptr, g_Q);
    cudaGetSymbolAddress((void**)&kvptr, g_KV);
    cudaGetSymbolAddress((void**)&aoptr, g_AO);

    // 1) Q projection: [2048,1024] = x @ Wq^T
    gemm_bias_k<<<dim3(DIMC / BN, (BATCH * NQ) / BM), 256>>>(
        x, Wq, nullptr, qptr, BATCH * NQ, DIMC, DIMC);

    // 2) KV projection: [4096,2048] = context @ Wkv^T + b_kv
    gemm_bias_k<<<dim3((2 * DIMC) / BN, (BATCH * MKV) / BM), 256>>>(
        context, Wkv, b_kv, kvptr, BATCH * MKV, 2 * DIMC, DIMC);

    // 3) Attention
    cudaFuncSetAttribute(attn_k, cudaFuncAttributeMaxDynamicSharedMemorySize,
                         ATTN_SMEM_BYTES);
    attn_k<<<dim3(NQ / TQ, NH, BATCH), 256, ATTN_SMEM_BYTES>>>(
        qptr, kvptr, mask, aoptr);

    // 4) Output projection: [2048,1024] = AO @ Wo^T
    gemm_bias_k<<<dim3(DIMC / BN, (BATCH * NQ) / BM), 256>>>(
        aoptr, Wo, nullptr, out, BATCH * NQ, DIMC, DIMC);
}

// round 3
// speedup vs baseline: 1.3507x; 1.3507x over previous
#include <cuda_runtime.h>
#include <cuda_bf16.h>
#include <math.h>
#include <stdint.h>

#define DIMC 1024
#define HD 64
#define NH 16
#define BATCH 2
#define NQ 1024
#define MKV 2048
#define ATT_SCALE 0.125f

// ---------------------------------------------------------------------------
// Scratch (no allocations allowed)
// ---------------------------------------------------------------------------
__device__ __align__(16) float g_Q[(size_t)BATCH * NQ * DIMC];        // 8 MB
__device__ __align__(16) float g_KV[(size_t)BATCH * MKV * 2 * DIMC];  // 32 MB
__device__ __align__(16) float g_AO[(size_t)BATCH * NQ * DIMC];       // 8 MB

__device__ __align__(16) __nv_bfloat16 gb_xh[(size_t)BATCH * NQ * DIMC];
__device__ __align__(16) __nv_bfloat16 gb_xl[(size_t)BATCH * NQ * DIMC];
__device__ __align__(16) __nv_bfloat16 gb_ch[(size_t)BATCH * MKV * DIMC];
__device__ __align__(16) __nv_bfloat16 gb_cl[(size_t)BATCH * MKV * DIMC];
__device__ __align__(16) __nv_bfloat16 gb_wqh[(size_t)DIMC * DIMC];
__device__ __align__(16) __nv_bfloat16 gb_wql[(size_t)DIMC * DIMC];
__device__ __align__(16) __nv_bfloat16 gb_wkvh[(size_t)2 * DIMC * DIMC];
__device__ __align__(16) __nv_bfloat16 gb_wkvl[(size_t)2 * DIMC * DIMC];
__device__ __align__(16) __nv_bfloat16 gb_woh[(size_t)DIMC * DIMC];
__device__ __align__(16) __nv_bfloat16 gb_wol[(size_t)DIMC * DIMC];
__device__ __align__(16) __nv_bfloat16 gb_aoh[(size_t)BATCH * NQ * DIMC];
__device__ __align__(16) __nv_bfloat16 gb_aol[(size_t)BATCH * NQ * DIMC];

// ---------------------------------------------------------------------------
// PTX helpers (sm_80+ compatible: mma.sync / ldmatrix / cp.async)
// ---------------------------------------------------------------------------
__device__ __forceinline__ uint32_t smem_u32(const void* p) {
    uint32_t a;
    asm("{ .reg .u64 t; cvta.to.shared.u64 t, %1; cvt.u32.u64 %0, t; }"
        : "=r"(a) : "l"(p));
    return a;
}

#define CP_ASYNC16(dst, src) \
    asm volatile("cp.async.cg.shared.global [%0], [%1], 16;" \
                 :: "r"(dst), "l"(src) : "memory")
#define CP_COMMIT() asm volatile("cp.async.commit_group;" ::: "memory")
#define CP_WAIT1()  asm volatile("cp.async.wait_group 1;" ::: "memory")
#define CP_WAIT0()  asm volatile("cp.async.wait_group 0;" ::: "memory")

__device__ __forceinline__ void ldsm_x4(uint32_t* r, uint32_t addr) {
    asm volatile("ldmatrix.sync.aligned.m8n8.x4.shared.b16 {%0,%1,%2,%3}, [%4];"
                 : "=r"(r[0]), "=r"(r[1]), "=r"(r[2]), "=r"(r[3]) : "r"(addr));
}

__device__ __forceinline__ void mma_bf16(float* c, const uint32_t* a, const uint32_t* b) {
    asm volatile(
        "mma.sync.aligned.m16n8k16.row.col.f32.bf16.bf16.f32 "
        "{%0,%1,%2,%3}, {%4,%5,%6,%7}, {%8,%9}, {%0,%1,%2,%3};"
        : "+f"(c[0]), "+f"(c[1]), "+f"(c[2]), "+f"(c[3])
        : "r"(a[0]), "r"(a[1]), "r"(a[2]), "r"(a[3]), "r"(b[0]), "r"(b[1]));
}

// ---------------------------------------------------------------------------
// Split fp32 -> bf16 hi + lo
// ---------------------------------------------------------------------------
__global__ void split_k(const float* __restrict__ in,
                        __nv_bfloat16* __restrict__ hi,
                        __nv_bfloat16* __restrict__ lo, int n)
{
    int i = blockIdx.x * blockDim.x + threadIdx.x;
    if (i < n) {
        float v = in[i];
        __nv_bfloat16 h = __float2bfloat16(v);
        hi[i] = h;
        lo[i] = __float2bfloat16(v - __bfloat162float(h));
    }
}

// ---------------------------------------------------------------------------
// Tensor-core GEMM: C[M,N] = (Ah+Al)[M,K] @ (Bh+Bl)[N,K]^T (+ bias)
// mma.sync.m16n8k16 bf16, fp32 accum. CTA tile 128x128, BK=32, 8 warps,
// warp tile 64x32. cp.async 2-stage pipeline, padded SMEM (80B row stride).
// Split product: hh + hl + lh.
// ---------------------------------------------------------------------------
#define BK 32
#define ROWB 80            // bytes per smem row (32 bf16 = 64B + 16B pad)
#define TILEB (128 * ROWB) // 10240 B per matrix tile
#define STAGEB (4 * TILEB) // Ah, Al, Bh, Bl
#define GEMM_SMEM (2 * STAGEB)  // 81920 B

__global__ __launch_bounds__(256) void gemm_tc(
    const __nv_bfloat16* __restrict__ Ah, const __nv_bfloat16* __restrict__ Al,
    const __nv_bfloat16* __restrict__ Bh, const __nv_bfloat16* __restrict__ Bl,
    const float* __restrict__ bias, float* __restrict__ C,
    int Ncols, int K)
{
    extern __shared__ char smem[];
    const uint32_t sb = smem_u32(smem);
    const int tid = threadIdx.x;
    const int wid = tid >> 5, lane = tid & 31;
    const int wm = wid & 1;        // warp row (0..1) -> 64 M rows each
    const int wn = wid >> 1;       // warp col (0..3) -> 32 N cols each
    const int bm = blockIdx.y * 128;
    const int bn = blockIdx.x * 128;

    const __nv_bfloat16* srcs[4] = {
        Ah + (size_t)bm * K, Al + (size_t)bm * K,
        Bh + (size_t)bn * K, Bl + (size_t)bn * K };

    const int ntiles = K / BK;

    // ---- async tile loader: 4 matrices x 128 rows x 2 chunks(16B)/row ----
    auto load_stage = [&](int t, int stage) {
        const uint32_t base = sb + stage * STAGEB;
#pragma unroll
        for (int m = 0; m < 4; m++) {
            const __nv_bfloat16* src = srcs[m] + (size_t)t * BK;
#pragma unroll
            for (int rep = 0; rep < 2; rep++) {
                int f = tid + rep * 256;     // 0..511
                int row = f >> 2;            // 0..127
                int ch = f & 3;              // 16B chunk
                CP_ASYNC16(base + m * TILEB + row * ROWB + ch * 16,
                           src + (size_t)row * K + ch * 8);
            }
        }
        CP_COMMIT();
    };

    float acc[4][4][4];  // [m16 tile][n8 tile][4]
#pragma unroll
    for (int i = 0; i < 4; i++)
#pragma unroll
        for (int j = 0; j < 4; j++)
#pragma unroll
            for (int k = 0; k < 4; k++) acc[i][j][k] = 0.f;

    load_stage(0, 0);

    // ldmatrix lane addressing (constant per thread)
    const int a_row = wm * 64 + (lane & 7) + 8 * ((lane >> 3) & 1);
    const int a_kof = 8 * (lane >> 4);
    const int b_row = wn * 32 + (lane & 7) + 8 * (lane >> 4);
    const int b_kof = 8 * ((lane >> 3) & 1);

    for (int t = 0; t < ntiles; t++) {
        const int stage = t & 1;
        if (t + 1 < ntiles) load_stage(t + 1, stage ^ 1);
        CP_WAIT1();
        __syncthreads();

        const uint32_t sA_h = sb + stage * STAGEB;
        const uint32_t sA_l = sA_h + TILEB;
        const uint32_t sB_h = sA_h + 2 * TILEB;
        const uint32_t sB_l = sA_h + 3 * TILEB;

#pragma unroll
        for (int kk = 0; kk < BK; kk += 16) {
            uint32_t a_h[4][4], a_l[4][4];
#pragma unroll
            for (int mt = 0; mt < 4; mt++) {
                uint32_t off = (uint32_t)(a_row + mt * 16) * ROWB + (kk + a_kof) * 2;
                ldsm_x4(a_h[mt], sA_h + off);
                ldsm_x4(a_l[mt], sA_l + off);
            }
            uint32_t b_h[8], b_l[8];
#pragma unroll
            for (int np = 0; np < 2; np++) {  // pairs of n8 tiles
                uint32_t off = (uint32_t)(b_row + np * 16) * ROWB + (kk + b_kof) * 2;
                ldsm_x4(b_h + np * 4, sB_h + off);
                ldsm_x4(b_l + np * 4, sB_l + off);
            }
#pragma unroll
            for (int mt = 0; mt < 4; mt++) {
#pragma unroll
                for (int nt = 0; nt < 4; nt++) {
                    mma_bf16(acc[mt][nt], a_h[mt], b_h + nt * 2);
                    mma_bf16(acc[mt][nt], a_h[mt], b_l + nt * 2);
                    mma_bf16(acc[mt][nt], a_l[mt], b_h + nt * 2);
                }
            }
        }
        __syncthreads();
    }

    // ---- epilogue: direct global stores (float2 per fragment row) ----
    const int er = lane >> 2;            // 0..7
    const int ec = (lane & 3) * 2;       // 0,2,4,6
#pragma unroll
    for (int mt = 0; mt < 4; mt++) {
        int row0 = bm + wm * 64 + mt * 16 + er;
#pragma unroll
        for (int nt = 0; nt < 4; nt++) {
            int col = bn + wn * 32 + nt * 8 + ec;
            float b0 = 0.f, b1 = 0.f;
            if (bias) { b0 = bias[col]; b1 = bias[col + 1]; }
            float2 v0 = make_float2(acc[mt][nt][0] + b0, acc[mt][nt][1] + b1);
            float2 v1 = make_float2(acc[mt][nt][2] + b0, acc[mt][nt][3] + b1);
            *(float2*)(C + (size_t)row0 * Ncols + col) = v0;
            *(float2*)(C + (size_t)(row0 + 8) * Ncols + col) = v1;
        }
    }
}

// ---------------------------------------------------------------------------
// Flash attention (fp32 SIMT, unchanged)
// ---------------------------------------------------------------------------
#define TQ 64
#define TK 64
#define LQD 65
#define LSK 65
#define ATTN_SMEM_FLOATS (4 * TQ * LQD + 3 * TQ)
#define ATTN_SMEM_BYTES (ATTN_SMEM_FLOATS * 4)

__global__ __launch_bounds__(256) void attn_k(
    const float* __restrict__ Q, const float* __restrict__ KV,
    const unsigned int* __restrict__ mask, float* __restrict__ AO)
{
    extern __shared__ float sm[];
    float* Qs = sm;
    float* Ks = Qs + TQ * LQD;
    float* Vs = Ks + TK * LQD;
    float* Ss = Vs + TK * LQD;
    float* m_s = Ss + TQ * LSK;
    float* l_s = m_s + TQ;
    float* a_s = l_s + TQ;

    const int qb = blockIdx.x;
    const int h  = blockIdx.y;
    const int b  = blockIdx.z;
    const int tid = threadIdx.x;
    const int tx = tid & 15, ty = tid >> 4;
    const int n0 = qb * TQ;

    for (int i = tid; i < TQ * (HD / 4); i += 256) {
        int r = i >> 4;
        int c4 = (i & 15) << 2;
        float4 v = *(const float4*)(Q + ((size_t)(b * NQ + n0 + r)) * DIMC + h * HD + c4);
        float* dst = &Qs[r * LQD + c4];
        dst[0] = v.x; dst[1] = v.y; dst[2] = v.z; dst[3] = v.w;
    }
    if (tid < TQ) { m_s[tid] = -1e30f; l_s[tid] = 0.f; }

    float o[4][4];
#pragma unroll
    for (int i = 0; i < 4; i++)
#pragma unroll
        for (int j = 0; j < 4; j++) o[i][j] = 0.f;

    __syncthreads();

    for (int m0 = 0; m0 < MKV; m0 += TK) {
        for (int i = tid; i < TK * (HD / 4); i += 256) {
            int r = i >> 4;
            int c4 = (i & 15) << 2;
            size_t base = ((size_t)(b * MKV + m0 + r)) * (2 * DIMC) + h * HD + c4;
            float4 kk4 = *(const float4*)(KV + base);
            float* kd = &Ks[r * LQD + c4];
            kd[0] = kk4.x; kd[1] = kk4.y; kd[2] = kk4.z; kd[3] = kk4.w;
            float4 vv4 = *(const float4*)(KV + base + DIMC);
            float* vd = &Vs[r * LQD + c4];
            vd[0] = vv4.x; vd[1] = vv4.y; vd[2] = vv4.z; vd[3] = vv4.w;
        }
        __syncthreads();

        float acc[4][4];
#pragma unroll
        for (int i = 0; i < 4; i++)
#pragma unroll
            for (int j = 0; j < 4; j++) acc[i][j] = 0.f;

        for (int d = 0; d < HD; d++) {
            float a[4], bb[4];
#pragma unroll
            for (int i = 0; i < 4; i++) a[i] = Qs[(ty * 4 + i) * LQD + d];
#pragma unroll
            for (int j = 0; j < 4; j++) bb[j] = Ks[(tx * 4 + j) * LQD + d];
#pragma unroll
            for (int i = 0; i < 4; i++)
#pragma unroll
                for (int j = 0; j < 4; j++)
                    acc[i][j] = fmaf(a[i], bb[j], acc[i][j]);
        }

#pragma unroll
        for (int i = 0; i < 4; i++) {
            int gn = n0 + ty * 4 + i;
#pragma unroll
            for (int j = 0; j < 4; j++) {
                int gm = m0 + tx * 4 + j;
                unsigned int mk = mask[((size_t)b * NQ + gn) * MKV + gm];
                Ss[(ty * 4 + i) * LSK + tx * 4 + j] =
                    mk ? acc[i][j] * ATT_SCALE : -1e30f;
            }
        }
        __syncthreads();

        {
            int w = tid >> 5, lane = tid & 31;
            for (int rr = 0; rr < 8; rr++) {
                int r = w * 8 + rr;
                float v1 = Ss[r * LSK + lane];
                float v2 = Ss[r * LSK + lane + 32];
                float mx = fmaxf(v1, v2);
#pragma unroll
                for (int off = 16; off; off >>= 1)
                    mx = fmaxf(mx, __shfl_xor_sync(0xffffffffu, mx, off));
                float m_old = m_s[r];
                float m_new = fmaxf(m_old, mx);
                float p1 = __expf(v1 - m_new);
                float p2 = __expf(v2 - m_new);
                Ss[r * LSK + lane] = p1;
                Ss[r * LSK + lane + 32] = p2;
                float s = p1 + p2;
#pragma unroll
                for (int off = 16; off; off >>= 1)
                    s += __shfl_xor_sync(0xffffffffu, s, off);
                if (lane == 0) {
                    float alpha = __expf(m_old - m_new);
                    l_s[r] = l_s[r] * alpha + s;
                    m_s[r] = m_new;
                    a_s[r] = alpha;
                }
            }
        }
        __syncthreads();

        float al[4];
#pragma unroll
        for (int i = 0; i < 4; i++) al[i] = a_s[ty * 4 + i];
#pragma unroll
        for (int i = 0; i < 4; i++)
#pragma unroll
            for (int j = 0; j < 4; j++) o[i][j] *= al[i];

        for (int kk = 0; kk < TK; kk++) {
            float p[4], vv[4];
#pragma unroll
            for (int i = 0; i < 4; i++) p[i] = Ss[(ty * 4 + i) * LSK + kk];
#pragma unroll
            for (int j = 0; j < 4; j++) vv[j] = Vs[kk * LQD + tx * 4 + j];
#pragma unroll
            for (int i = 0; i < 4; i++)
#pragma unroll
                for (int j = 0; j < 4; j++)
                    o[i][j] = fmaf(p[i], vv[j], o[i][j]);
        }
        __syncthreads();
    }

#pragma unroll
    for (int i = 0; i < 4; i++) {
        int r = ty * 4 + i;
        float inv = 1.0f / l_s[r];
#pragma unroll
        for (int j = 0; j < 4; j++) {
            AO[((size_t)(b * NQ + n0 + r)) * DIMC + h * HD + tx * 4 + j] = o[i][j] * inv;
        }
    }
}

// ---------------------------------------------------------------------------
// Launch
// ---------------------------------------------------------------------------
static void run_split(const float* in, __nv_bfloat16* hi, __nv_bfloat16* lo, int n)
{
    split_k<<<(n + 255) / 256, 256>>>(in, hi, lo, n);
}

extern "C" void kernel_launch(void* const* d_in, const int* in_sizes, int n_in,
                              void* d_out, int out_size)
{
    const float* x        = (const float*)d_in[0];
    const float* context  = (const float*)d_in[1];
    const unsigned int* mask = (const unsigned int*)d_in[2];
    const float* Wq       = (const float*)d_in[3];
    const float* Wkv      = (const float*)d_in[4];
    const float* b_kv     = (const float*)d_in[5];
    const float* Wo       = (const float*)d_in[6];
    float* out            = (float*)d_out;

    float *qptr, *kvptr, *aoptr;
    cudaGetSymbolAddress((void**)&qptr, g_Q);
    cudaGetSymbolAddress((void**)&kvptr, g_KV);
    cudaGetSymbolAddress((void**)&aoptr, g_AO);

    __nv_bfloat16 *xh, *xl, *ch, *cl, *wqh, *wql, *wkvh, *wkvl, *woh, *wol, *aoh, *aol;
    cudaGetSymbolAddress((void**)&xh, gb_xh);   cudaGetSymbolAddress((void**)&xl, gb_xl);
    cudaGetSymbolAddress((void**)&ch, gb_ch);   cudaGetSymbolAddress((void**)&cl, gb_cl);
    cudaGetSymbolAddress((void**)&wqh, gb_wqh); cudaGetSymbolAddress((void**)&wql, gb_wql);
    cudaGetSymbolAddress((void**)&wkvh, gb_wkvh); cudaGetSymbolAddress((void**)&wkvl, gb_wkvl);
    cudaGetSymbolAddress((void**)&woh, gb_woh); cudaGetSymbolAddress((void**)&wol, gb_wol);
    cudaGetSymbolAddress((void**)&aoh, gb_aoh); cudaGetSymbolAddress((void**)&aol, gb_aol);

    cudaFuncSetAttribute(gemm_tc, cudaFuncAttributeMaxDynamicSharedMemorySize, GEMM_SMEM);
    cudaFuncSetAttribute(attn_k, cudaFuncAttributeMaxDynamicSharedMemorySize, ATTN_SMEM_BYTES);

    run_split(x, xh, xl, BATCH * NQ * DIMC);
    run_split(Wq, wqh, wql, DIMC * DIMC);
    run_split(context, ch, cl, BATCH * MKV * DIMC);
    run_split(Wkv, wkvh, wkvl, 2 * DIMC * DIMC);
    run_split(Wo, woh, wol, DIMC * DIMC);

    // 1) Q = x @ Wq^T : [2048, 1024]
    gemm_tc<<<dim3(DIMC / 128, (BATCH * NQ) / 128), 256, GEMM_SMEM>>>(
        xh, xl, wqh, wql, nullptr, qptr, DIMC, DIMC);

    // 2) KV = context @ Wkv^T + b_kv : [4096, 2048]
    gemm_tc<<<dim3((2 * DIMC) / 128, (BATCH * MKV) / 128), 256, GEMM_SMEM>>>(
        ch, cl, wkvh, wkvl, b_kv, kvptr, 2 * DIMC, DIMC);

    // 3) attention (fp32)
    attn_k<<<dim3(NQ / TQ, NH, BATCH), 256, ATTN_SMEM_BYTES>>>(
        qptr, kvptr, mask, aoptr);

    // 4) out = AO @ Wo^T : [2048, 1024]
    run_split(aoptr, aoh, aol, BATCH * NQ * DIMC);
    gemm_tc<<<dim3(DIMC / 128, (BATCH * NQ) / 128), 256, GEMM_SMEM>>>(
        aoh, aol, woh, wol, nullptr, out, DIMC, DIMC);
}

// round 4
// speedup vs baseline: 2.8025x; 2.0749x over previous
#include <cuda_runtime.h>
#include <cuda_bf16.h>
#include <math.h>
#include <stdint.h>

#define DIMC 1024
#define HD 64
#define NH 16
#define BATCH 2
#define NQ 1024
#define MKV 2048
#define ATT_SCALE 0.125f

// ---------------------------------------------------------------------------
// Scratch
// ---------------------------------------------------------------------------
__device__ __align__(16) __nv_bfloat16 gb_xh[(size_t)BATCH * NQ * DIMC];
__device__ __align__(16) __nv_bfloat16 gb_xl[(size_t)BATCH * NQ * DIMC];
__device__ __align__(16) __nv_bfloat16 gb_ch[(size_t)BATCH * MKV * DIMC];
__device__ __align__(16) __nv_bfloat16 gb_cl[(size_t)BATCH * MKV * DIMC];
__device__ __align__(16) __nv_bfloat16 gb_wqh[(size_t)DIMC * DIMC];
__device__ __align__(16) __nv_bfloat16 gb_wql[(size_t)DIMC * DIMC];
__device__ __align__(16) __nv_bfloat16 gb_wkvh[(size_t)2 * DIMC * DIMC];
__device__ __align__(16) __nv_bfloat16 gb_wkvl[(size_t)2 * DIMC * DIMC];
__device__ __align__(16) __nv_bfloat16 gb_woh[(size_t)DIMC * DIMC];
__device__ __align__(16) __nv_bfloat16 gb_wol[(size_t)DIMC * DIMC];
__device__ __align__(16) __nv_bfloat16 gb_aoh[(size_t)BATCH * NQ * DIMC];
__device__ __align__(16) __nv_bfloat16 gb_aol[(size_t)BATCH * NQ * DIMC];
// per-head layouts
__device__ __align__(16) __nv_bfloat16 g_qh[(size_t)BATCH * NH * NQ * HD];
__device__ __align__(16) __nv_bfloat16 g_ql[(size_t)BATCH * NH * NQ * HD];
__device__ __align__(16) __nv_bfloat16 g_kh[(size_t)BATCH * NH * MKV * HD];
__device__ __align__(16) __nv_bfloat16 g_kl[(size_t)BATCH * NH * MKV * HD];
__device__ __align__(16) __nv_bfloat16 g_vh[(size_t)BATCH * NH * MKV * HD];
__device__ __align__(16) __nv_bfloat16 g_vl[(size_t)BATCH * NH * MKV * HD];
__device__ __align__(16) __nv_bfloat16 g_bias[(size_t)BATCH * NQ * MKV];

// ---------------------------------------------------------------------------
// PTX helpers
// ---------------------------------------------------------------------------
__device__ __forceinline__ uint32_t smem_u32(const void* p) {
    uint32_t a;
    asm("{ .reg .u64 t; cvta.to.shared.u64 t, %1; cvt.u32.u64 %0, t; }"
        : "=r"(a) : "l"(p));
    return a;
}

#define CP_ASYNC16(dst, src) \
    asm volatile("cp.async.cg.shared.global [%0], [%1], 16;" \
                 :: "r"(dst), "l"(src) : "memory")
#define CP_COMMIT() asm volatile("cp.async.commit_group;" ::: "memory")
#define CP_WAIT2()  asm volatile("cp.async.wait_group 2;" ::: "memory")
#define CP_WAIT1()  asm volatile("cp.async.wait_group 1;" ::: "memory")
#define CP_WAIT0()  asm volatile("cp.async.wait_group 0;" ::: "memory")

__device__ __forceinline__ void ldsm_x4(uint32_t* r, uint32_t addr) {
    asm volatile("ldmatrix.sync.aligned.m8n8.x4.shared.b16 {%0,%1,%2,%3}, [%4];"
                 : "=r"(r[0]), "=r"(r[1]), "=r"(r[2]), "=r"(r[3]) : "r"(addr));
}
__device__ __forceinline__ void ldsm_x4_t(uint32_t* r, uint32_t addr) {
    asm volatile("ldmatrix.sync.aligned.m8n8.x4.trans.shared.b16 {%0,%1,%2,%3}, [%4];"
                 : "=r"(r[0]), "=r"(r[1]), "=r"(r[2]), "=r"(r[3]) : "r"(addr));
}
__device__ __forceinline__ void mma_bf16(float* c, const uint32_t* a, const uint32_t* b) {
    asm volatile(
        "mma.sync.aligned.m16n8k16.row.col.f32.bf16.bf16.f32 "
        "{%0,%1,%2,%3}, {%4,%5,%6,%7}, {%8,%9}, {%0,%1,%2,%3};"
        : "+f"(c[0]), "+f"(c[1]), "+f"(c[2]), "+f"(c[3])
        : "r"(a[0]), "r"(a[1]), "r"(a[2]), "r"(a[3]), "r"(b[0]), "r"(b[1]));
}

__device__ __forceinline__ void store_split(__nv_bfloat16* H, __nv_bfloat16* L,
                                            size_t idx, float v0, float v1) {
    __nv_bfloat16 h0 = __float2bfloat16(v0), h1 = __float2bfloat16(v1);
    __nv_bfloat162 hh; hh.x = h0; hh.y = h1;
    *(__nv_bfloat162*)(H + idx) = hh;
    __nv_bfloat162 ll;
    ll.x = __float2bfloat16(v0 - __bfloat162float(h0));
    ll.y = __float2bfloat16(v1 - __bfloat162float(h1));
    *(__nv_bfloat162*)(L + idx) = ll;
}

__device__ __forceinline__ void split_pack(float a, float b, uint32_t& hi, uint32_t& lo) {
    __nv_bfloat16 ha = __float2bfloat16(a), hb = __float2bfloat16(b);
    __nv_bfloat162 H; H.x = ha; H.y = hb;
    hi = *(uint32_t*)&H;
    __nv_bfloat162 L;
    L.x = __float2bfloat16(a - __bfloat162float(ha));
    L.y = __float2bfloat16(b - __bfloat162float(hb));
    lo = *(uint32_t*)&L;
}

// ---------------------------------------------------------------------------
// Prep kernels
// ---------------------------------------------------------------------------
__global__ void split_k(const float* __restrict__ in,
                        __nv_bfloat16* __restrict__ hi,
                        __nv_bfloat16* __restrict__ lo, int n)
{
    int i = blockIdx.x * blockDim.x + threadIdx.x;
    if (i < n) {
        float v = in[i];
        __nv_bfloat16 h = __float2bfloat16(v);
        hi[i] = h;
        lo[i] = __float2bfloat16(v - __bfloat162float(h));
    }
}

__global__ void mask_bias_k(const unsigned int* __restrict__ mask,
                            __nv_bfloat16* __restrict__ bias, int n)
{
    int i = blockIdx.x * blockDim.x + threadIdx.x;
    if (i < n)
        bias[i] = mask[i] ? __float2bfloat16(0.f) : __float2bfloat16(-30000.f);
}

// ---------------------------------------------------------------------------
// Tensor-core GEMM with fused split epilogues.
// MODE 0: C fp32.  MODE 1: Q split -> [b,h,n,d].  MODE 2: KV split.
// ---------------------------------------------------------------------------
#define BK 32
#define ROWB 80
#define TILEB (128 * ROWB)
#define STAGEB (4 * TILEB)
#define GEMM_SMEM (2 * STAGEB)

template<int MODE>
__global__ __launch_bounds__(256) void gemm_tc(
    const __nv_bfloat16* __restrict__ Ah, const __nv_bfloat16* __restrict__ Al,
    const __nv_bfloat16* __restrict__ Bh, const __nv_bfloat16* __restrict__ Bl,
    const float* __restrict__ bias, float* __restrict__ C,
    __nv_bfloat16* __restrict__ H0, __nv_bfloat16* __restrict__ L0,
    __nv_bfloat16* __restrict__ H1, __nv_bfloat16* __restrict__ L1,
    int Ncols, int K)
{
    extern __shared__ char smem[];
    const uint32_t sb = smem_u32(smem);
    const int tid = threadIdx.x;
    const int wid = tid >> 5, lane = tid & 31;
    const int wm = wid & 1;
    const int wn = wid >> 1;
    const int bm = blockIdx.y * 128;
    const int bn = blockIdx.x * 128;

    const __nv_bfloat16* srcs[4] = {
        Ah + (size_t)bm * K, Al + (size_t)bm * K,
        Bh + (size_t)bn * K, Bl + (size_t)bn * K };

    const int ntiles = K / BK;

    auto load_stage = [&](int t, int stage) {
        const uint32_t base = sb + stage * STAGEB;
#pragma unroll
        for (int m = 0; m < 4; m++) {
            const __nv_bfloat16* src = srcs[m] + (size_t)t * BK;
#pragma unroll
            for (int rep = 0; rep < 2; rep++) {
                int f = tid + rep * 256;
                int row = f >> 2;
                int ch = f & 3;
                CP_ASYNC16(base + m * TILEB + row * ROWB + ch * 16,
                           src + (size_t)row * K + ch * 8);
            }
        }
        CP_COMMIT();
    };

    float acc[4][4][4];
#pragma unroll
    for (int i = 0; i < 4; i++)
#pragma unroll
        for (int j = 0; j < 4; j++)
#pragma unroll
            for (int k = 0; k < 4; k++) acc[i][j][k] = 0.f;

    load_stage(0, 0);

    const int a_row = wm * 64 + (lane & 7) + 8 * ((lane >> 3) & 1);
    const int a_kof = 8 * (lane >> 4);
    const int b_row = wn * 32 + (lane & 7) + 8 * (lane >> 4);
    const int b_kof = 8 * ((lane >> 3) & 1);

    for (int t = 0; t < ntiles; t++) {
        const int stage = t & 1;
        if (t + 1 < ntiles) { load_stage(t + 1, stage ^ 1); CP_WAIT1(); }
        else                { CP_WAIT0(); }
        __syncthreads();

        const uint32_t sA_h = sb + stage * STAGEB;
        const uint32_t sA_l = sA_h + TILEB;
        const uint32_t sB_h = sA_h + 2 * TILEB;
        const uint32_t sB_l = sA_h + 3 * TILEB;

#pragma unroll
        for (int kk = 0; kk < BK; kk += 16) {
            uint32_t a_h[4][4], a_l[4][4];
#pragma unroll
            for (int mt = 0; mt < 4; mt++) {
                uint32_t off = (uint32_t)(a_row + mt * 16) * ROWB + (kk + a_kof) * 2;
                ldsm_x4(a_h[mt], sA_h + off);
                ldsm_x4(a_l[mt], sA_l + off);
            }
            uint32_t b_h[8], b_l[8];
#pragma unroll
            for (int np = 0; np < 2; np++) {
                uint32_t off = (uint32_t)(b_row + np * 16) * ROWB + (kk + b_kof) * 2;
                ldsm_x4(b_h + np * 4, sB_h + off);
                ldsm_x4(b_l + np * 4, sB_l + off);
            }
#pragma unroll
            for (int mt = 0; mt < 4; mt++) {
#pragma unroll
                for (int nt = 0; nt < 4; nt++) {
                    mma_bf16(acc[mt][nt], a_h[mt], b_h + nt * 2);
                    mma_bf16(acc[mt][nt], a_h[mt], b_l + nt * 2);
                    mma_bf16(acc[mt][nt], a_l[mt], b_h + nt * 2);
                }
            }
        }
        __syncthreads();
    }

    const int er = lane >> 2;
    const int ec = (lane & 3) * 2;
#pragma unroll
    for (int mt = 0; mt < 4; mt++) {
        int row0 = bm + wm * 64 + mt * 16 + er;
#pragma unroll
        for (int nt = 0; nt < 4; nt++) {
            int col = bn + wn * 32 + nt * 8 + ec;
            float b0 = 0.f, b1 = 0.f;
            if (bias) { b0 = bias[col]; b1 = bias[col + 1]; }
            float v00 = acc[mt][nt][0] + b0, v01 = acc[mt][nt][1] + b1;
            float v10 = acc[mt][nt][2] + b0, v11 = acc[mt][nt][3] + b1;
            if (MODE == 0) {
                *(float2*)(C + (size_t)row0 * Ncols + col) = make_float2(v00, v01);
                *(float2*)(C + (size_t)(row0 + 8) * Ncols + col) = make_float2(v10, v11);
            } else if (MODE == 1) {
#pragma unroll
                for (int rr = 0; rr < 2; rr++) {
                    int row = row0 + rr * 8;
                    int b_ = row >> 10, n_ = row & 1023;
                    int h_ = col >> 6, d_ = col & 63;
                    size_t idx = ((size_t)(b_ * NH + h_) * NQ + n_) * HD + d_;
                    store_split(H0, L0, idx, rr ? v10 : v00, rr ? v11 : v01);
                }
            } else {
                int kv = col >> 10;
                int h_ = (col >> 6) & 15, d_ = col & 63;
#pragma unroll
                for (int rr = 0; rr < 2; rr++) {
                    int row = row0 + rr * 8;
                    int b_ = row >> 11, m_ = row & 2047;
                    size_t idx = ((size_t)(b_ * NH + h_) * MKV + m_) * HD + d_;
                    if (kv == 0) store_split(H0, L0, idx, rr ? v10 : v00, rr ? v11 : v01);
                    else         store_split(H1, L1, idx, rr ? v10 : v00, rr ? v11 : v01);
                }
            }
        }
    }
}

// ---------------------------------------------------------------------------
// Tensor-core flash attention.
// CTA: 128 q rows x head, 8 warps (16 rows each). 64-key tiles, 32 iters.
// S = Qh*Kh + Qh*Kl + Ql*Kh ; O += Ph*Vh + Ph*Vl + Pl*Vh. fp32 softmax in regs.
// ---------------------------------------------------------------------------
#define AT_ROWB 144
#define AT_QTILE (128 * AT_ROWB)
#define AT_KTILE (64 * AT_ROWB)
#define AT_STAGE (4 * AT_KTILE + 128 * AT_ROWB)
#define AT_SMEM (2 * AT_QTILE + 2 * AT_STAGE)
#define AT_NT (MKV / 64)

__global__ __launch_bounds__(256) void attn_tc(
    const __nv_bfloat16* __restrict__ Qh, const __nv_bfloat16* __restrict__ Ql,
    const __nv_bfloat16* __restrict__ Kh, const __nv_bfloat16* __restrict__ Kl,
    const __nv_bfloat16* __restrict__ Vh, const __nv_bfloat16* __restrict__ Vl,
    const __nv_bfloat16* __restrict__ Bias,
    __nv_bfloat16* __restrict__ AOh, __nv_bfloat16* __restrict__ AOl)
{
    extern __shared__ char smem[];
    const uint32_t sb = smem_u32(smem);
    const int tid = threadIdx.x, wid = tid >> 5, lane = tid & 31;
    const int h = blockIdx.y, b = blockIdx.z;
    const int n0 = blockIdx.x * 128;
    const size_t qbase = ((size_t)(b * NH + h) * NQ + n0) * HD;
    const size_t kvbase = (size_t)(b * NH + h) * MKV * HD;
    const size_t bbase = ((size_t)b * NQ + n0) * MKV;

    // Q hi/lo -> smem (group 0)
    for (int i = tid; i < 2048; i += 256) {
        int t = i >> 10, r = (i >> 3) & 127, c = i & 7;
        const __nv_bfloat16* src = (t ? Ql : Qh) + qbase + (size_t)r * HD + c * 8;
        CP_ASYNC16(sb + t * AT_QTILE + r * AT_ROWB + c * 16, src);
    }
    CP_COMMIT();

    auto load_stage = [&](int t, int s) {
        const uint32_t base = sb + 2 * AT_QTILE + s * AT_STAGE;
        const int m0 = t * 64;
        for (int i = tid; i < 2048; i += 256) {
            int mt = i >> 9, r = (i >> 3) & 63, c = i & 7;
            const __nv_bfloat16* p =
                (mt == 0 ? Kh : mt == 1 ? Kl : mt == 2 ? Vh : Vl)
                + kvbase + (size_t)(m0 + r) * HD + c * 8;
            CP_ASYNC16(base + mt * AT_KTILE + r * AT_ROWB + c * 16, p);
        }
        for (int i = tid; i < 1024; i += 256) {
            int r = i >> 3, c = i & 7;
            CP_ASYNC16(base + 4 * AT_KTILE + r * AT_ROWB + c * 16,
                       Bias + bbase + (size_t)r * MKV + m0 + c * 8);
        }
        CP_COMMIT();
    };

    load_stage(0, 0);
    load_stage(1, 1);
    CP_WAIT2();          // Q done
    __syncthreads();

    // Q fragments (held in regs for the whole kernel)
    uint32_t qh[4][4], ql[4][4];
    const int wrow = wid * 16;
    {
        const int lr = wrow + ((lane >> 3) & 1) * 8 + (lane & 7);
#pragma unroll
        for (int ks = 0; ks < 4; ks++) {
            uint32_t off = (uint32_t)lr * AT_ROWB + (ks * 16 + (lane >> 4) * 8) * 2;
            ldsm_x4(qh[ks], sb + off);
            ldsm_x4(ql[ks], sb + AT_QTILE + off);
        }
    }

    float o[8][4];
#pragma unroll
    for (int i = 0; i < 8; i++)
#pragma unroll
        for (int j = 0; j < 4; j++) o[i][j] = 0.f;
    float m0r = -1e30f, m1r = -1e30f, l0r = 0.f, l1r = 0.f;
    const int er = lane >> 2, ec = (lane & 3) * 2;

    const int krow = ((lane >> 4) & 1) * 8 + (lane & 7);
    const int kcol = ((lane >> 3) & 1) * 8;

    for (int t = 0; t < AT_NT; t++) {
        if (t == AT_NT - 1) CP_WAIT0(); else CP_WAIT1();
        __syncthreads();
        const uint32_t stg = sb + 2 * AT_QTILE + (t & 1) * AT_STAGE;
        const char* stgp = smem + 2 * AT_QTILE + (size_t)(t & 1) * AT_STAGE;

        // ---- S = Q K^T (3-way split) ----
        float s[8][4];
#pragma unroll
        for (int i = 0; i < 8; i++)
#pragma unroll
            for (int j = 0; j < 4; j++) s[i][j] = 0.f;

#pragma unroll
        for (int ks = 0; ks < 4; ks++) {
#pragma unroll
            for (int jm = 0; jm < 4; jm++) {
                uint32_t off = (uint32_t)(jm * 16 + krow) * AT_ROWB + (ks * 16 + kcol) * 2;
                uint32_t bh[4], bl[4];
                ldsm_x4(bh, stg + off);
                ldsm_x4(bl, stg + AT_KTILE + off);
                mma_bf16(s[2 * jm],     qh[ks], bh);
                mma_bf16(s[2 * jm + 1], qh[ks], bh + 2);
                mma_bf16(s[2 * jm],     qh[ks], bl);
                mma_bf16(s[2 * jm + 1], qh[ks], bl + 2);
                mma_bf16(s[2 * jm],     ql[ks], bh);
                mma_bf16(s[2 * jm + 1], ql[ks], bh + 2);
            }
        }

        // ---- scale + mask bias ----
        const char* bs = stgp + 4 * AT_KTILE;
#pragma unroll
        for (int nt = 0; nt < 8; nt++) {
            __nv_bfloat162 b0 = *(const __nv_bfloat162*)(bs + (wrow + er) * AT_ROWB + (nt * 8 + ec) * 2);
            __nv_bfloat162 b1 = *(const __nv_bfloat162*)(bs + (wrow + er + 8) * AT_ROWB + (nt * 8 + ec) * 2);
            s[nt][0] = s[nt][0] * ATT_SCALE + __bfloat162float(b0.x);
            s[nt][1] = s[nt][1] * ATT_SCALE + __bfloat162float(b0.y);
            s[nt][2] = s[nt][2] * ATT_SCALE + __bfloat162float(b1.x);
            s[nt][3] = s[nt][3] * ATT_SCALE + __bfloat162float(b1.y);
        }

        // ---- online softmax (rows er and er+8) ----
        float mx0 = -1e30f, mx1 = -1e30f;
#pragma unroll
        for (int nt = 0; nt < 8; nt++) {
            mx0 = fmaxf(mx0, fmaxf(s[nt][0], s[nt][1]));
            mx1 = fmaxf(mx1, fmaxf(s[nt][2], s[nt][3]));
        }
        mx0 = fmaxf(mx0, __shfl_xor_sync(0xffffffffu, mx0, 1));
        mx0 = fmaxf(mx0, __shfl_xor_sync(0xffffffffu, mx0, 2));
        mx1 = fmaxf(mx1, __shfl_xor_sync(0xffffffffu, mx1, 1));
        mx1 = fmaxf(mx1, __shfl_xor_sync(0xffffffffu, mx1, 2));
        float mn0 = fmaxf(m0r, mx0), mn1 = fmaxf(m1r, mx1);
        float al0 = __expf(m0r - mn0), al1 = __expf(m1r - mn1);
        m0r = mn0; m1r = mn1;

        float sum0 = 0.f, sum1 = 0.f;
#pragma unroll
        for (int nt = 0; nt < 8; nt++) {
            s[nt][0] = __expf(s[nt][0] - mn0);
            s[nt][1] = __expf(s[nt][1] - mn0);
            s[nt][2] = __expf(s[nt][2] - mn1);
            s[nt][3] = __expf(s[nt][3] - mn1);
            sum0 += s[nt][0] + s[nt][1];
            sum1 += s[nt][2] + s[nt][3];
        }
        sum0 += __shfl_xor_sync(0xffffffffu, sum0, 1);
        sum0 += __shfl_xor_sync(0xffffffffu, sum0, 2);
        sum1 += __shfl_xor_sync(0xffffffffu, sum1, 1);
        sum1 += __shfl_xor_sync(0xffffffffu, sum1, 2);
        l0r = l0r * al0 + sum0;
        l1r = l1r * al1 + sum1;

#pragma unroll
        for (int nt = 0; nt < 8; nt++) {
            o[nt][0] *= al0; o[nt][1] *= al0;
            o[nt][2] *= al1; o[nt][3] *= al1;
        }

        // ---- P fragments (hi/lo) from S registers ----
        uint32_t ph[4][4], pl[4][4];
#pragma unroll
        for (int ks = 0; ks < 4; ks++) {
            split_pack(s[2 * ks][0],     s[2 * ks][1],     ph[ks][0], pl[ks][0]);
            split_pack(s[2 * ks][2],     s[2 * ks][3],     ph[ks][1], pl[ks][1]);
            split_pack(s[2 * ks + 1][0], s[2 * ks + 1][1], ph[ks][2], pl[ks][2]);
            split_pack(s[2 * ks + 1][2], s[2 * ks + 1][3], ph[ks][3], pl[ks][3]);
        }

        // ---- O += P V (3-way split) ----
#pragma unroll
        for (int ks = 0; ks < 4; ks++) {
#pragma unroll
            for (int jd = 0; jd < 4; jd++) {
                uint32_t off = (uint32_t)(ks * 16 + ((lane >> 3) & 1) * 8 + (lane & 7)) * AT_ROWB
                             + (jd * 16 + (lane >> 4) * 8) * 2;
                uint32_t bv[4], bvl[4];
                ldsm_x4_t(bv,  stg + 2 * AT_KTILE + off);
                ldsm_x4_t(bvl, stg + 3 * AT_KTILE + off);
                mma_bf16(o[2 * jd],     ph[ks], bv);
                mma_bf16(o[2 * jd + 1], ph[ks], bv + 2);
                mma_bf16(o[2 * jd],     ph[ks], bvl);
                mma_bf16(o[2 * jd + 1], ph[ks], bvl + 2);
                mma_bf16(o[2 * jd],     pl[ks], bv);
                mma_bf16(o[2 * jd + 1], pl[ks], bv + 2);
            }
        }

        __syncthreads();
        if (t + 2 < AT_NT) load_stage(t + 2, t & 1);
    }

    // ---- epilogue: normalize, split to bf16 hi/lo, store [b*NQ+n, h*64+d] ----
    float inv0 = 1.f / l0r, inv1 = 1.f / l1r;
#pragma unroll
    for (int nt = 0; nt < 8; nt++) {
        int col = h * HD + nt * 8 + ec;
        size_t i0 = ((size_t)b * NQ + n0 + wrow + er) * DIMC + col;
        size_t i1 = ((size_t)b * NQ + n0 + wrow + er + 8) * DIMC + col;
        store_split(AOh, AOl, i0, o[nt][0] * inv0, o[nt][1] * inv0);
        store_split(AOh, AOl, i1, o[nt][2] * inv1, o[nt][3] * inv1);
    }
}

// ---------------------------------------------------------------------------
// Launch
// ---------------------------------------------------------------------------
static void run_split(const float* in, __nv_bfloat16* hi, __nv_bfloat16* lo, int n)
{
    split_k<<<(n + 255) / 256, 256>>>(in, hi, lo, n);
}

extern "C" void kernel_launch(void* const* d_in, const int* in_sizes, int n_in,
                              void* d_out, int out_size)
{
    const float* x        = (const float*)d_in[0];
    const float* context  = (const float*)d_in[1];
    const unsigned int* mask = (const unsigned int*)d_in[2];
    const float* Wq       = (const float*)d_in[3];
    const float* Wkv      = (const float*)d_in[4];
    const float* b_kv     = (const float*)d_in[5];
    const float* Wo       = (const float*)d_in[6];
    float* out            = (float*)d_out;

    __nv_bfloat16 *xh, *xl, *ch, *cl, *wqh, *wql, *wkvh, *wkvl, *woh, *wol, *aoh, *aol;
    __nv_bfloat16 *qh, *ql, *kh, *kl, *vh, *vl, *bias;
    cudaGetSymbolAddress((void**)&xh, gb_xh);   cudaGetSymbolAddress((void**)&xl, gb_xl);
    cudaGetSymbolAddress((void**)&ch, gb_ch);   cudaGetSymbolAddress((void**)&cl, gb_cl);
    cudaGetSymbolAddress((void**)&wqh, gb_wqh); cudaGetSymbolAddress((void**)&wql, gb_wql);
    cudaGetSymbolAddress((void**)&wkvh, gb_wkvh); cudaGetSymbolAddress((void**)&wkvl, gb_wkvl);
    cudaGetSymbolAddress((void**)&woh, gb_woh); cudaGetSymbolAddress((void**)&wol, gb_wol);
    cudaGetSymbolAddress((void**)&aoh, gb_aoh); cudaGetSymbolAddress((void**)&aol, gb_aol);
    cudaGetSymbolAddress((void**)&qh, g_qh); cudaGetSymbolAddress((void**)&ql, g_ql);
    cudaGetSymbolAddress((void**)&kh, g_kh); cudaGetSymbolAddress((void**)&kl, g_kl);
    cudaGetSymbolAddress((void**)&vh, g_vh); cudaGetSymbolAddress((void**)&vl, g_vl);
    cudaGetSymbolAddress((void**)&bias, g_bias);

    cudaFuncSetAttribute(gemm_tc<0>, cudaFuncAttributeMaxDynamicSharedMemorySize, GEMM_SMEM);
    cudaFuncSetAttribute(gemm_tc<1>, cudaFuncAttributeMaxDynamicSharedMemorySize, GEMM_SMEM);
    cudaFuncSetAttribute(gemm_tc<2>, cudaFuncAttributeMaxDynamicSharedMemorySize, GEMM_SMEM);
    cudaFuncSetAttribute(attn_tc, cudaFuncAttributeMaxDynamicSharedMemorySize, AT_SMEM);

    run_split(x, xh, xl, BATCH * NQ * DIMC);
    run_split(Wq, wqh, wql, DIMC * DIMC);
    run_split(context, ch, cl, BATCH * MKV * DIMC);
    run_split(Wkv, wkvh, wkvl, 2 * DIMC * DIMC);
    run_split(Wo, woh, wol, DIMC * DIMC);
    mask_bias_k<<<(BATCH * NQ * MKV + 255) / 256, 256>>>(mask, bias, BATCH * NQ * MKV);

    // 1) Q projection -> per-head bf16 split
    gemm_tc<1><<<dim3(DIMC / 128, (BATCH * NQ) / 128), 256, GEMM_SMEM>>>(
        xh, xl, wqh, wql, nullptr, nullptr, qh, ql, nullptr, nullptr, DIMC, DIMC);

    // 2) KV projection -> per-head bf16 split (K and V)
    gemm_tc<2><<<dim3((2 * DIMC) / 128, (BATCH * MKV) / 128), 256, GEMM_SMEM>>>(
        ch, cl, wkvh, wkvl, b_kv, nullptr, kh, kl, vh, vl, 2 * DIMC, DIMC);

    // 3) tensor-core flash attention -> AO bf16 split
    attn_tc<<<dim3(NQ / 128, NH, BATCH), 256, AT_SMEM>>>(
        qh, ql, kh, kl, vh, vl, bias, aoh, aol);

    // 4) output projection -> fp32 out
    gemm_tc<0><<<dim3(DIMC / 128, (BATCH * NQ) / 128), 256, GEMM_SMEM>>>(
        aoh, aol, woh, wol, nullptr, out, nullptr, nullptr, nullptr, nullptr, DIMC, DIMC);
}

// round 5
// speedup vs baseline: 3.3062x; 1.1797x over previous
#include <cuda_runtime.h>
#include <cuda_bf16.h>
#include <cuda_fp16.h>
#include <math.h>
#include <stdint.h>

#define DIMC 1024
#define HD 64
#define NH 16
#define BATCH 2
#define NQ 1024
#define MKV 2048
#define ATT_SCALE 0.125f
#define L2E 1.4426950408889634f

// ---------------------------------------------------------------------------
// Scratch (__device__ globals; kernels reference them directly)
// ---------------------------------------------------------------------------
__device__ __align__(16) __nv_bfloat16 gb_xh[(size_t)BATCH * NQ * DIMC];
__device__ __align__(16) __nv_bfloat16 gb_xl[(size_t)BATCH * NQ * DIMC];
__device__ __align__(16) __nv_bfloat16 gb_ch[(size_t)BATCH * MKV * DIMC];
__device__ __align__(16) __nv_bfloat16 gb_cl[(size_t)BATCH * MKV * DIMC];
__device__ __align__(16) __nv_bfloat16 gb_wqh[(size_t)DIMC * DIMC];
__device__ __align__(16) __nv_bfloat16 gb_wql[(size_t)DIMC * DIMC];
__device__ __align__(16) __nv_bfloat16 gb_wkvh[(size_t)2 * DIMC * DIMC];
__device__ __align__(16) __nv_bfloat16 gb_wkvl[(size_t)2 * DIMC * DIMC];
__device__ __align__(16) __nv_bfloat16 gb_woh[(size_t)DIMC * DIMC];
__device__ __align__(16) __nv_bfloat16 gb_wol[(size_t)DIMC * DIMC];
__device__ __align__(16) __nv_bfloat16 gb_aoh[(size_t)BATCH * NQ * DIMC];
__device__ __align__(16) __nv_bfloat16 gb_aol[(size_t)BATCH * NQ * DIMC];
__device__ __align__(16) __nv_bfloat16 g_qh[(size_t)BATCH * NH * NQ * HD];
__device__ __align__(16) __nv_bfloat16 g_ql[(size_t)BATCH * NH * NQ * HD];
__device__ __align__(16) __nv_bfloat16 g_kh[(size_t)BATCH * NH * MKV * HD];
__device__ __align__(16) __nv_bfloat16 g_kl[(size_t)BATCH * NH * MKV * HD];
__device__ __align__(16) __nv_bfloat16 g_vh[(size_t)BATCH * NH * MKV * HD];
__device__ __align__(16) __nv_bfloat16 g_vl[(size_t)BATCH * NH * MKV * HD];
__device__ __align__(16) __nv_bfloat16 g_bias[(size_t)BATCH * NQ * MKV];

// ---------------------------------------------------------------------------
// PTX helpers
// ---------------------------------------------------------------------------
__device__ __forceinline__ uint32_t smem_u32(const void* p) {
    uint32_t a;
    asm("{ .reg .u64 t; cvta.to.shared.u64 t, %1; cvt.u32.u64 %0, t; }"
        : "=r"(a) : "l"(p));
    return a;
}

#define CP_ASYNC16(dst, src) \
    asm volatile("cp.async.cg.shared.global [%0], [%1], 16;" \
                 :: "r"(dst), "l"(src) : "memory")
#define CP_COMMIT() asm volatile("cp.async.commit_group;" ::: "memory")
#define CP_WAIT2()  asm volatile("cp.async.wait_group 2;" ::: "memory")
#define CP_WAIT1()  asm volatile("cp.async.wait_group 1;" ::: "memory")
#define CP_WAIT0()  asm volatile("cp.async.wait_group 0;" ::: "memory")

__device__ __forceinline__ void ldsm_x4(uint32_t* r, uint32_t addr) {
    asm volatile("ldmatrix.sync.aligned.m8n8.x4.shared.b16 {%0,%1,%2,%3}, [%4];"
                 : "=r"(r[0]), "=r"(r[1]), "=r"(r[2]), "=r"(r[3]) : "r"(addr));
}
__device__ __forceinline__ void ldsm_x4_t(uint32_t* r, uint32_t addr) {
    asm volatile("ldmatrix.sync.aligned.m8n8.x4.trans.shared.b16 {%0,%1,%2,%3}, [%4];"
                 : "=r"(r[0]), "=r"(r[1]), "=r"(r[2]), "=r"(r[3]) : "r"(addr));
}
__device__ __forceinline__ void mma_bf16(float* c, const uint32_t* a, const uint32_t* b) {
    asm volatile(
        "mma.sync.aligned.m16n8k16.row.col.f32.bf16.bf16.f32 "
        "{%0,%1,%2,%3}, {%4,%5,%6,%7}, {%8,%9}, {%0,%1,%2,%3};"
        : "+f"(c[0]), "+f"(c[1]), "+f"(c[2]), "+f"(c[3])
        : "r"(a[0]), "r"(a[1]), "r"(a[2]), "r"(a[3]), "r"(b[0]), "r"(b[1]));
}

// exp2 of two fp32 args via one f16x2 MUFU op; returns {exp2(a), exp2(b)}
__device__ __forceinline__ float2 exp2_h2(float a, float b) {
    uint32_t h;
    asm("cvt.rn.f16x2.f32 %0, %1, %2;" : "=r"(h) : "f"(b), "f"(a)); // hi=b, lo=a
    asm("ex2.approx.f16x2 %0, %0;" : "+r"(h));
    __half2 v = *reinterpret_cast<__half2*>(&h);
    float2 r;
    r.x = __half2float(v.x);
    r.y = __half2float(v.y);
    return r;
}

__device__ __forceinline__ void store_split(__nv_bfloat16* H, __nv_bfloat16* L,
                                            size_t idx, float v0, float v1) {
    __nv_bfloat16 h0 = __float2bfloat16(v0), h1 = __float2bfloat16(v1);
    __nv_bfloat162 hh; hh.x = h0; hh.y = h1;
    *(__nv_bfloat162*)(H + idx) = hh;
    __nv_bfloat162 ll;
    ll.x = __float2bfloat16(v0 - __bfloat162float(h0));
    ll.y = __float2bfloat16(v1 - __bfloat162float(h1));
    *(__nv_bfloat162*)(L + idx) = ll;
}

__device__ __forceinline__ void split_pack(float a, float b, uint32_t& hi, uint32_t& lo) {
    __nv_bfloat16 ha = __float2bfloat16(a), hb = __float2bfloat16(b);
    __nv_bfloat162 H; H.x = ha; H.y = hb;
    hi = *(uint32_t*)&H;
    __nv_bfloat162 L;
    L.x = __float2bfloat16(a - __bfloat162float(ha));
    L.y = __float2bfloat16(b - __bfloat162float(hb));
    lo = *(uint32_t*)&L;
}

// ---------------------------------------------------------------------------
// Fused prep: 5 fp32->bf16(hi/lo) splits + mask->bf16 bias, one launch.
// ---------------------------------------------------------------------------
#define NXQ ((BATCH * NQ * DIMC) / 4)
#define NWQQ ((DIMC * DIMC) / 4)
#define NCTXQ ((BATCH * MKV * DIMC) / 4)
#define NWKVQ ((2 * DIMC * DIMC) / 4)
#define NWOQ ((DIMC * DIMC) / 4)
#define NMASKQ ((BATCH * NQ * MKV) / 4)
#define PREP_SPLITQ (NXQ + NWQQ + NCTXQ + NWKVQ + NWOQ)
#define PREP_TOTALQ (PREP_SPLITQ + NMASKQ)

__global__ void prep_k(const float* __restrict__ x, const float* __restrict__ Wq,
                       const float* __restrict__ ctx, const float* __restrict__ Wkv,
                       const float* __restrict__ Wo, const unsigned int* __restrict__ mask)
{
    int i = blockIdx.x * blockDim.x + threadIdx.x;
    const int q0 = NXQ, q1 = q0 + NWQQ, q2 = q1 + NCTXQ, q3 = q2 + NWKVQ, q4 = q3 + NWOQ;

    if (i < q4) {
        const float* src; __nv_bfloat16 *H, *L; int off = i;
        if (i < q0)      { src = x;   H = gb_xh;   L = gb_xl; }
        else if (i < q1) { src = Wq;  H = gb_wqh;  L = gb_wql;  off -= q0; }
        else if (i < q2) { src = ctx; H = gb_ch;   L = gb_cl;   off -= q1; }
        else if (i < q3) { src = Wkv; H = gb_wkvh; L = gb_wkvl; off -= q2; }
        else             { src = Wo;  H = gb_woh;  L = gb_wol;  off -= q3; }
        float4 v = ((const float4*)src)[off];
        __nv_bfloat16 h0 = __float2bfloat16(v.x), h1 = __float2bfloat16(v.y);
        __nv_bfloat16 h2 = __float2bfloat16(v.z), h3 = __float2bfloat16(v.w);
        __nv_bfloat162 hp0, hp1, lp0, lp1;
        hp0.x = h0; hp0.y = h1; hp1.x = h2; hp1.y = h3;
        lp0.x = __float2bfloat16(v.x - __bfloat162float(h0));
        lp0.y = __float2bfloat16(v.y - __bfloat162float(h1));
        lp1.x = __float2bfloat16(v.z - __bfloat162float(h2));
        lp1.y = __float2bfloat16(v.w - __bfloat162float(h3));
        uint2 hp, lp;
        hp.x = *(uint32_t*)&hp0; hp.y = *(uint32_t*)&hp1;
        lp.x = *(uint32_t*)&lp0; lp.y = *(uint32_t*)&lp1;
        ((uint2*)H)[off] = hp;
        ((uint2*)L)[off] = lp;
    } else if (i < PREP_TOTALQ) {
        int off = i - q4;
        uint4 m = ((const uint4*)mask)[off];
        const __nv_bfloat16 z = __float2bfloat16(0.f);
        const __nv_bfloat16 neg = __float2bfloat16(-30000.f);
        __nv_bfloat162 b0, b1;
        b0.x = m.x ? z : neg; b0.y = m.y ? z : neg;
        b1.x = m.z ? z : neg; b1.y = m.w ? z : neg;
        uint2 bp;
        bp.x = *(uint32_t*)&b0; bp.y = *(uint32_t*)&b1;
        ((uint2*)g_bias)[off] = bp;
    }
}

// ---------------------------------------------------------------------------
// Shared GEMM mainloop (K=1024): 128x128 CTA tile, BK=32, 8 warps (2x4),
// cp.async 2-stage, 3-way split product hh+hl+lh.
// ---------------------------------------------------------------------------
#define BK 32
#define GK 1024
#define GNT (GK / BK)
#define ROWB 80
#define TILEB (128 * ROWB)
#define STAGEB (4 * TILEB)
#define GEMM_SMEM (2 * STAGEB)

__device__ __forceinline__ void gemm_mainloop(
    uint32_t sb, int tid,
    const __nv_bfloat16* __restrict__ Ah, const __nv_bfloat16* __restrict__ Al,
    const __nv_bfloat16* __restrict__ Bh, const __nv_bfloat16* __restrict__ Bl,
    float acc[4][4][4])
{
    const int wid = tid >> 5, lane = tid & 31;
    const int wm = wid & 1;
    const int wn = wid >> 1;
    const __nv_bfloat16* srcs[4] = { Ah, Al, Bh, Bl };

    auto load_stage = [&](int t, int stage) {
        const uint32_t base = sb + stage * STAGEB;
#pragma unroll
        for (int m = 0; m < 4; m++) {
            const __nv_bfloat16* src = srcs[m] + (size_t)t * BK;
#pragma unroll
            for (int rep = 0; rep < 2; rep++) {
                int f = tid + rep * 256;
                int row = f >> 2;
                int ch = f & 3;
                CP_ASYNC16(base + m * TILEB + row * ROWB + ch * 16,
                           src + (size_t)row * GK + ch * 8);
            }
        }
        CP_COMMIT();
    };

    load_stage(0, 0);

    const int a_row = wm * 64 + (lane & 7) + 8 * ((lane >> 3) & 1);
    const int a_kof = 8 * (lane >> 4);
    const int b_row = wn * 32 + (lane & 7) + 8 * (lane >> 4);
    const int b_kof = 8 * ((lane >> 3) & 1);

    for (int t = 0; t < GNT; t++) {
        const int stage = t & 1;
        if (t + 1 < GNT) { load_stage(t + 1, stage ^ 1); CP_WAIT1(); }
        else             { CP_WAIT0(); }
        __syncthreads();

        const uint32_t sA_h = sb + stage * STAGEB;
        const uint32_t sA_l = sA_h + TILEB;
        const uint32_t sB_h = sA_h + 2 * TILEB;
        const uint32_t sB_l = sA_h + 3 * TILEB;

#pragma unroll
        for (int kk = 0; kk < BK; kk += 16) {
            uint32_t a_h[4][4], a_l[4][4];
#pragma unroll
            for (int mt = 0; mt < 4; mt++) {
                uint32_t off = (uint32_t)(a_row + mt * 16) * ROWB + (kk + a_kof) * 2;
                ldsm_x4(a_h[mt], sA_h + off);
                ldsm_x4(a_l[mt], sA_l + off);
            }
            uint32_t b_h[8], b_l[8];
#pragma unroll
            for (int np = 0; np < 2; np++) {
                uint32_t off = (uint32_t)(b_row + np * 16) * ROWB + (kk + b_kof) * 2;
                ldsm_x4(b_h + np * 4, sB_h + off);
                ldsm_x4(b_l + np * 4, sB_l + off);
            }
#pragma unroll
            for (int mt = 0; mt < 4; mt++) {
#pragma unroll
                for (int nt = 0; nt < 4; nt++) {
                    mma_bf16(acc[mt][nt], a_h[mt], b_h + nt * 2);
                    mma_bf16(acc[mt][nt], a_h[mt], b_l + nt * 2);
                    mma_bf16(acc[mt][nt], a_l[mt], b_h + nt * 2);
                }
            }
        }
        __syncthreads();
    }
}

// ---------------------------------------------------------------------------
// Merged Q + KV projection (640 CTAs). KV CTAs first (longer pole).
// ---------------------------------------------------------------------------
__global__ __launch_bounds__(256) void proj_tc(const float* __restrict__ b_kv)
{
    extern __shared__ char smem[];
    const uint32_t sb = smem_u32(smem);
    const int tid = threadIdx.x;
    const int wid = tid >> 5, lane = tid & 31;
    const int wm = wid & 1, wn = wid >> 1;
    const int bid = blockIdx.x;

    const __nv_bfloat16 *pAh, *pAl, *pBh, *pBl;
    int bm, bn;
    bool kvmode;
    if (bid < 512) {
        kvmode = true;
        bm = (bid >> 4) * 128; bn = (bid & 15) * 128;
        pAh = gb_ch; pAl = gb_cl; pBh = gb_wkvh; pBl = gb_wkvl;
    } else {
        kvmode = false;
        int q = bid - 512;
        bm = (q >> 3) * 128; bn = (q & 7) * 128;
        pAh = gb_xh; pAl = gb_xl; pBh = gb_wqh; pBl = gb_wql;
    }

    float acc[4][4][4];
#pragma unroll
    for (int i = 0; i < 4; i++)
#pragma unroll
        for (int j = 0; j < 4; j++)
#pragma unroll
            for (int k = 0; k < 4; k++) acc[i][j][k] = 0.f;

    gemm_mainloop(sb, tid,
                  pAh + (size_t)bm * GK, pAl + (size_t)bm * GK,
                  pBh + (size_t)bn * GK, pBl + (size_t)bn * GK, acc);

    const int er = lane >> 2;
    const int ec = (lane & 3) * 2;
#pragma unroll
    for (int mt = 0; mt < 4; mt++) {
        int row0 = bm + wm * 64 + mt * 16 + er;
#pragma unroll
        for (int nt = 0; nt < 4; nt++) {
            int col = bn + wn * 32 + nt * 8 + ec;
            float b0 = 0.f, b1 = 0.f;
            if (kvmode) { b0 = b_kv[col]; b1 = b_kv[col + 1]; }
            float v00 = acc[mt][nt][0] + b0, v01 = acc[mt][nt][1] + b1;
            float v10 = acc[mt][nt][2] + b0, v11 = acc[mt][nt][3] + b1;
            if (!kvmode) {
#pragma unroll
                for (int rr = 0; rr < 2; rr++) {
                    int row = row0 + rr * 8;
                    int b_ = row >> 10, n_ = row & 1023;
                    int h_ = col >> 6, d_ = col & 63;
                    size_t idx = ((size_t)(b_ * NH + h_) * NQ + n_) * HD + d_;
                    store_split(g_qh, g_ql, idx, rr ? v10 : v00, rr ? v11 : v01);
                }
            } else {
                int kv = col >> 10;
                int h_ = (col >> 6) & 15, d_ = col & 63;
#pragma unroll
                for (int rr = 0; rr < 2; rr++) {
                    int row = row0 + rr * 8;
                    int b_ = row >> 11, m_ = row & 2047;
                    size_t idx = ((size_t)(b_ * NH + h_) * MKV + m_) * HD + d_;
                    if (kv == 0) store_split(g_kh, g_kl, idx, rr ? v10 : v00, rr ? v11 : v01);
                    else         store_split(g_vh, g_vl, idx, rr ? v10 : v00, rr ? v11 : v01);
                }
            }
        }
    }
}

// ---------------------------------------------------------------------------
// Output projection: out = AO @ Wo^T (fp32 store)
// ---------------------------------------------------------------------------
__global__ __launch_bounds__(256) void out_tc(float* __restrict__ C)
{
    extern __shared__ char smem[];
    const uint32_t sb = smem_u32(smem);
    const int tid = threadIdx.x;
    const int wid = tid >> 5, lane = tid & 31;
    const int wm = wid & 1, wn = wid >> 1;
    const int bm = blockIdx.y * 128;
    const int bn = blockIdx.x * 128;

    float acc[4][4][4];
#pragma unroll
    for (int i = 0; i < 4; i++)
#pragma unroll
        for (int j = 0; j < 4; j++)
#pragma unroll
            for (int k = 0; k < 4; k++) acc[i][j][k] = 0.f;

    gemm_mainloop(sb, tid,
                  gb_aoh + (size_t)bm * GK, gb_aol + (size_t)bm * GK,
                  gb_woh + (size_t)bn * GK, gb_wol + (size_t)bn * GK, acc);

    const int er = lane >> 2;
    const int ec = (lane & 3) * 2;
#pragma unroll
    for (int mt = 0; mt < 4; mt++) {
        int row0 = bm + wm * 64 + mt * 16 + er;
#pragma unroll
        for (int nt = 0; nt < 4; nt++) {
            int col = bn + wn * 32 + nt * 8 + ec;
            *(float2*)(C + (size_t)row0 * DIMC + col) =
                make_float2(acc[mt][nt][0], acc[mt][nt][1]);
            *(float2*)(C + (size_t)(row0 + 8) * DIMC + col) =
                make_float2(acc[mt][nt][2], acc[mt][nt][3]);
        }
    }
}

// ---------------------------------------------------------------------------
// Tensor-core flash attention with f16x2 exp.
// ---------------------------------------------------------------------------
#define AT_ROWB 144
#define AT_QTILE (128 * AT_ROWB)
#define AT_KTILE (64 * AT_ROWB)
#define AT_STAGE (4 * AT_KTILE + 128 * AT_ROWB)
#define AT_SMEM (2 * AT_QTILE + 2 * AT_STAGE)
#define AT_NT (MKV / 64)

__global__ __launch_bounds__(256) void attn_tc()
{
    extern __shared__ char smem[];
    const uint32_t sb = smem_u32(smem);
    const int tid = threadIdx.x, wid = tid >> 5, lane = tid & 31;
    const int h = blockIdx.y, b = blockIdx.z;
    const int n0 = blockIdx.x * 128;
    const size_t qbase = ((size_t)(b * NH + h) * NQ + n0) * HD;
    const size_t kvbase = (size_t)(b * NH + h) * MKV * HD;
    const size_t bbase = ((size_t)b * NQ + n0) * MKV;

    for (int i = tid; i < 2048; i += 256) {
        int t = i >> 10, r = (i >> 3) & 127, c = i & 7;
        const __nv_bfloat16* src = (t ? g_ql : g_qh) + qbase + (size_t)r * HD + c * 8;
        CP_ASYNC16(sb + t * AT_QTILE + r * AT_ROWB + c * 16, src);
    }
    CP_COMMIT();

    auto load_stage = [&](int t, int s) {
        const uint32_t base = sb + 2 * AT_QTILE + s * AT_STAGE;
        const int m0 = t * 64;
        for (int i = tid; i < 2048; i += 256) {
            int mt = i >> 9, r = (i >> 3) & 63, c = i & 7;
            const __nv_bfloat16* p =
                (mt == 0 ? g_kh : mt == 1 ? g_kl : mt == 2 ? g_vh : g_vl)
                + kvbase + (size_t)(m0 + r) * HD + c * 8;
            CP_ASYNC16(base + mt * AT_KTILE + r * AT_ROWB + c * 16, p);
        }
        for (int i = tid; i < 1024; i += 256) {
            int r = i >> 3, c = i & 7;
            CP_ASYNC16(base + 4 * AT_KTILE + r * AT_ROWB + c * 16,
                       g_bias + bbase + (size_t)r * MKV + m0 + c * 8);
        }
        CP_COMMIT();
    };

    load_stage(0, 0);
    load_stage(1, 1);
    CP_WAIT2();
    __syncthreads();

    uint32_t qh[4][4], ql[4][4];
    const int wrow = wid * 16;
    {
        const int lr = wrow + ((lane >> 3) & 1) * 8 + (lane & 7);
#pragma unroll
        for (int ks = 0; ks < 4; ks++) {
            uint32_t off = (uint32_t)lr * AT_ROWB + (ks * 16 + (lane >> 4) * 8) * 2;
            ldsm_x4(qh[ks], sb + off);
            ldsm_x4(ql[ks], sb + AT_QTILE + off);
        }
    }

    float o[8][4];
#pragma unroll
    for (int i = 0; i < 8; i++)
#pragma unroll
        for (int j = 0; j < 4; j++) o[i][j] = 0.f;
    float m0r = -1e30f, m1r = -1e30f, l0r = 0.f, l1r = 0.f;
    const int er = lane >> 2, ec = (lane & 3) * 2;

    const int krow = ((lane >> 4) & 1) * 8 + (lane & 7);
    const int kcol = ((lane >> 3) & 1) * 8;

    for (int t = 0; t < AT_NT; t++) {
        if (t == AT_NT - 1) CP_WAIT0(); else CP_WAIT1();
        __syncthreads();
        const uint32_t stg = sb + 2 * AT_QTILE + (t & 1) * AT_STAGE;
        const char* stgp = smem + 2 * AT_QTILE + (size_t)(t & 1) * AT_STAGE;

        // ---- S = Q K^T (3-way split) ----
        float s[8][4];
#pragma unroll
        for (int i = 0; i < 8; i++)
#pragma unroll
            for (int j = 0; j < 4; j++) s[i][j] = 0.f;

#pragma unroll
        for (int ks = 0; ks < 4; ks++) {
#pragma unroll
            for (int jm = 0; jm < 4; jm++) {
                uint32_t off = (uint32_t)(jm * 16 + krow) * AT_ROWB + (ks * 16 + kcol) * 2;
                uint32_t bh[4], bl[4];
                ldsm_x4(bh, stg + off);
                ldsm_x4(bl, stg + AT_KTILE + off);
                mma_bf16(s[2 * jm],     qh[ks], bh);
                mma_bf16(s[2 * jm + 1], qh[ks], bh + 2);
                mma_bf16(s[2 * jm],     qh[ks], bl);
                mma_bf16(s[2 * jm + 1], qh[ks], bl + 2);
                mma_bf16(s[2 * jm],     ql[ks], bh);
                mma_bf16(s[2 * jm + 1], ql[ks], bh + 2);
            }
        }

        // ---- scale + mask bias ----
        const char* bs = stgp + 4 * AT_KTILE;
#pragma unroll
        for (int nt = 0; nt < 8; nt++) {
            __nv_bfloat162 b0 = *(const __nv_bfloat162*)(bs + (wrow + er) * AT_ROWB + (nt * 8 + ec) * 2);
            __nv_bfloat162 b1 = *(const __nv_bfloat162*)(bs + (wrow + er + 8) * AT_ROWB + (nt * 8 + ec) * 2);
            s[nt][0] = s[nt][0] * ATT_SCALE + __bfloat162float(b0.x);
            s[nt][1] = s[nt][1] * ATT_SCALE + __bfloat162float(b0.y);
            s[nt][2] = s[nt][2] * ATT_SCALE + __bfloat162float(b1.x);
            s[nt][3] = s[nt][3] * ATT_SCALE + __bfloat162float(b1.y);
        }

        // ---- online softmax (rows er and er+8) ----
        float mx0 = -1e30f, mx1 = -1e30f;
#pragma unroll
        for (int nt = 0; nt < 8; nt++) {
            mx0 = fmaxf(mx0, fmaxf(s[nt][0], s[nt][1]));
            mx1 = fmaxf(mx1, fmaxf(s[nt][2], s[nt][3]));
        }
        mx0 = fmaxf(mx0, __shfl_xor_sync(0xffffffffu, mx0, 1));
        mx0 = fmaxf(mx0, __shfl_xor_sync(0xffffffffu, mx0, 2));
        mx1 = fmaxf(mx1, __shfl_xor_sync(0xffffffffu, mx1, 1));
        mx1 = fmaxf(mx1, __shfl_xor_sync(0xffffffffu, mx1, 2));
        float mn0 = fmaxf(m0r, mx0), mn1 = fmaxf(m1r, mx1);
        float al0 = __expf(m0r - mn0), al1 = __expf(m1r - mn1);
        m0r = mn0; m1r = mn1;

        // f16x2 exp2: arg = (s - m) * log2(e) in fp32, exp in f16 MUFU
        const float c0 = mn0 * L2E, c1 = mn1 * L2E;
        float sum0 = 0.f, sum1 = 0.f;
#pragma unroll
        for (int nt = 0; nt < 8; nt++) {
            float2 e01 = exp2_h2(fmaf(s[nt][0], L2E, -c0), fmaf(s[nt][1], L2E, -c0));
            float2 e23 = exp2_h2(fmaf(s[nt][2], L2E, -c1), fmaf(s[nt][3], L2E, -c1));
            s[nt][0] = e01.x; s[nt][1] = e01.y;
            s[nt][2] = e23.x; s[nt][3] = e23.y;
            sum0 += e01.x + e01.y;
            sum1 += e23.x + e23.y;
        }
        sum0 += __shfl_xor_sync(0xffffffffu, sum0, 1);
        sum0 += __shfl_xor_sync(0xffffffffu, sum0, 2);
        sum1 += __shfl_xor_sync(0xffffffffu, sum1, 1);
        sum1 += __shfl_xor_sync(0xffffffffu, sum1, 2);
        l0r = l0r * al0 + sum0;
        l1r = l1r * al1 + sum1;

#pragma unroll
        for (int nt = 0; nt < 8; nt++) {
            o[nt][0] *= al0; o[nt][1] *= al0;
            o[nt][2] *= al1; o[nt][3] *= al1;
        }

        // ---- P fragments (hi/lo) ----
        uint32_t ph[4][4], pl[4][4];
#pragma unroll
        for (int ks = 0; ks < 4; ks++) {
            split_pack(s[2 * ks][0],     s[2 * ks][1],     ph[ks][0], pl[ks][0]);
            split_pack(s[2 * ks][2],     s[2 * ks][3],     ph[ks][1], pl[ks][1]);
            split_pack(s[2 * ks + 1][0], s[2 * ks + 1][1], ph[ks][2], pl[ks][2]);
            split_pack(s[2 * ks + 1][2], s[2 * ks + 1][3], ph[ks][3], pl[ks][3]);
        }

        // ---- O += P V (3-way split) ----
#pragma unroll
        for (int ks = 0; ks < 4; ks++) {
#pragma unroll
            for (int jd = 0; jd < 4; jd++) {
                uint32_t off = (uint32_t)(ks * 16 + ((lane >> 3) & 1) * 8 + (lane & 7)) * AT_ROWB
                             + (jd * 16 + (lane >> 4) * 8) * 2;
                uint32_t bv[4], bvl[4];
                ldsm_x4_t(bv,  stg + 2 * AT_KTILE + off);
                ldsm_x4_t(bvl, stg + 3 * AT_KTILE + off);
                mma_bf16(o[2 * jd],     ph[ks], bv);
                mma_bf16(o[2 * jd + 1], ph[ks], bv + 2);
                mma_bf16(o[2 * jd],     ph[ks], bvl);
                mma_bf16(o[2 * jd + 1], ph[ks], bvl + 2);
                mma_bf16(o[2 * jd],     pl[ks], bv);
                mma_bf16(o[2 * jd + 1], pl[ks], bv + 2);
            }
        }

        __syncthreads();
        if (t + 2 < AT_NT) load_stage(t + 2, t & 1);
    }

    // ---- epilogue ----
    float inv0 = 1.f / l0r, inv1 = 1.f / l1r;
#pragma unroll
    for (int nt = 0; nt < 8; nt++) {
        int col = h * HD + nt * 8 + ec;
        size_t i0 = ((size_t)b * NQ + n0 + wrow + er) * DIMC + col;
        size_t i1 = ((size_t)b * NQ + n0 + wrow + er + 8) * DIMC + col;
        store_split(gb_aoh, gb_aol, i0, o[nt][0] * inv0, o[nt][1] * inv0);
        store_split(gb_aoh, gb_aol, i1, o[nt][2] * inv1, o[nt][3] * inv1);
    }
}

// ---------------------------------------------------------------------------
// Launch
// ---------------------------------------------------------------------------
extern "C" void kernel_launch(void* const* d_in, const int* in_sizes, int n_in,
                              void* d_out, int out_size)
{
    const float* x        = (const float*)d_in[0];
    const float* context  = (const float*)d_in[1];
    const unsigned int* mask = (const unsigned int*)d_in[2];
    const float* Wq       = (const float*)d_in[3];
    const float* Wkv      = (const float*)d_in[4];
    const float* b_kv     = (const float*)d_in[5];
    const float* Wo       = (const float*)d_in[6];
    float* out            = (float*)d_out;

    cudaFuncSetAttribute(proj_tc, cudaFuncAttributeMaxDynamicSharedMemorySize, GEMM_SMEM);
    cudaFuncSetAttribute(out_tc, cudaFuncAttributeMaxDynamicSharedMemorySize, GEMM_SMEM);
    cudaFuncSetAttribute(attn_tc, cudaFuncAttributeMaxDynamicSharedMemorySize, AT_SMEM);

    // 1) fused prep: splits + mask bias
    prep_k<<<(PREP_TOTALQ + 255) / 256, 256>>>(x, Wq, context, Wkv, Wo, mask);

    // 2) merged Q + KV projections
    proj_tc<<<640, 256, GEMM_SMEM>>>(b_kv);

    // 3) tensor-core flash attention
    attn_tc<<<dim3(NQ / 128, NH, BATCH), 256, AT_SMEM>>>();

    // 4) output projection
    out_tc<<<dim3(DIMC / 128, (BATCH * NQ) / 128), 256, GEMM_SMEM>>>(out);
}